// round 4
// baseline (speedup 1.0000x reference)
#include <cuda_runtime.h>
#include <cuda_bf16.h>
#include <math_constants.h>

// MultiLocalCosineLinear:
//   B=65536 rows, D=768, C=100 classes, P=C*(C-1)/2=4950 pairs.
//   per row: top2(first_out) -> (a<b) -> pair = b*(b-1)/2+a
//            logits[k] = sigma[pair] * cos(x, W[pair,k]),  k=0,1
//            pred = (logits[1] > logits[0]) ? b : a   (argmax, first-on-tie)
//   out (float32): [0,B) preds, [B, 3B) logits row-major (B,2)
//
// Warp-per-row. x row cached in 24 registers/lane (6 x float4), weight rows
// (30 MB table, L2-resident) streamed with norm computed in-flight.

#define NROWS   65536
#define DDIM    768
#define NCLS    100
#define F4_PER_LANE 6            // 768 floats / 4 / 32 lanes

__device__ __forceinline__ float warp_sum(float v) {
    #pragma unroll
    for (int o = 16; o; o >>= 1) v += __shfl_xor_sync(0xffffffffu, v, o);
    return v;
}

__global__ __launch_bounds__(256, 8)
void mlcl_kernel(const float* __restrict__ x,
                 const float* __restrict__ first_out,
                 const float* __restrict__ weights,
                 const float* __restrict__ sigma,
                 float* __restrict__ out)
{
    const int warp_id = blockIdx.x * 8 + (threadIdx.x >> 5);
    const int lane    = threadIdx.x & 31;
    if (warp_id >= NROWS) return;
    const int row = warp_id;

    // ---- top-2 over first_out[row, 0:100], jax.lax.top_k tie-break ----
    const float* fo = first_out + (size_t)row * NCLS;
    float v1 = -CUDART_INF_F, v2 = -CUDART_INF_F;
    int   i1 = NCLS,          i2 = NCLS;
    #pragma unroll
    for (int c = lane; c < NCLS; c += 32) {
        float v = __ldg(fo + c);
        if (v > v1) { v2 = v1; i2 = i1; v1 = v; i1 = c; }
        else if (v > v2) { v2 = v; i2 = c; }
        // (increasing c: equal values never displace an earlier index)
    }
    #pragma unroll
    for (int off = 16; off; off >>= 1) {
        float w1 = __shfl_xor_sync(0xffffffffu, v1, off);
        int   j1 = __shfl_xor_sync(0xffffffffu, i1, off);
        float w2 = __shfl_xor_sync(0xffffffffu, v2, off);
        int   j2 = __shfl_xor_sync(0xffffffffu, i2, off);
        // merge {v1,v2} with {w1,w2}; better = larger value, ties -> lower idx
        bool w1_best = (w1 > v1) || (w1 == v1 && j1 < i1);
        if (w1_best) {
            bool v1_second = (v1 > w2) || (v1 == w2 && i1 < j2);
            v2 = v1_second ? v1 : w2;
            i2 = v1_second ? i1 : j2;
            v1 = w1; i1 = j1;
        } else {
            bool w1_second = (w1 > v2) || (w1 == v2 && j1 < i2);
            if (w1_second) { v2 = w1; i2 = j1; }
        }
    }
    const int a = min(i1, i2);
    const int b = max(i1, i2);
    const long long pair = (long long)b * (b - 1) / 2 + a;

    // ---- load x row into registers, accumulate ||x||^2 ----
    const float4* x4 = (const float4*)(x + (size_t)row * DDIM);
    float4 xf[F4_PER_LANE];
    float xss = 0.f;
    #pragma unroll
    for (int j = 0; j < F4_PER_LANE; ++j) {
        float4 v = __ldg(x4 + lane + 32 * j);
        xf[j] = v;
        xss = fmaf(v.x, v.x, fmaf(v.y, v.y, fmaf(v.z, v.z, fmaf(v.w, v.w, xss))));
    }
    xss = warp_sum(xss);

    // ---- dots + weight norms for both rows of the gathered pair ----
    float logit[2];
    const float xinv = 1.0f / fmaxf(sqrtf(xss), 1e-12f);
    const float sg = __ldg(sigma + pair);
    #pragma unroll
    for (int k = 0; k < 2; ++k) {
        const float4* w4 = (const float4*)(weights + ((size_t)pair * 2 + k) * DDIM);
        float dot = 0.f, wss = 0.f;
        #pragma unroll
        for (int j = 0; j < F4_PER_LANE; ++j) {
            float4 w = __ldg(w4 + lane + 32 * j);
            dot = fmaf(w.x, xf[j].x, fmaf(w.y, xf[j].y,
                  fmaf(w.z, xf[j].z, fmaf(w.w, xf[j].w, dot))));
            wss = fmaf(w.x, w.x, fmaf(w.y, w.y,
                  fmaf(w.z, w.z, fmaf(w.w, w.w, wss))));
        }
        dot = warp_sum(dot);
        wss = warp_sum(wss);
        const float winv = 1.0f / fmaxf(sqrtf(wss), 1e-12f);
        logit[k] = sg * dot * xinv * winv;
    }

    if (lane == 0) {
        const int pred = (logit[1] > logit[0]) ? b : a;   // argmax: first on tie
        out[row] = (float)pred;
        out[(size_t)NROWS + 2 * (size_t)row + 0] = logit[0];
        out[(size_t)NROWS + 2 * (size_t)row + 1] = logit[1];
    }
}

extern "C" void kernel_launch(void* const* d_in, const int* in_sizes, int n_in,
                              void* d_out, int out_size) {
    const float* x        = (const float*)d_in[0];
    const float* first_o  = (const float*)d_in[1];
    const float* weights  = (const float*)d_in[2];
    const float* sigma    = (const float*)d_in[3];
    float* out = (float*)d_out;

    const int warps_per_block = 8;
    const int blocks = NROWS / warps_per_block;   // 8192
    mlcl_kernel<<<blocks, 256>>>(x, first_o, weights, sigma, out);
}

// round 5
// speedup vs baseline: 1.2309x; 1.2309x over previous
#include <cuda_runtime.h>
#include <cuda_bf16.h>
#include <math_constants.h>

// MultiLocalCosineLinear:
//   B=65536 rows, D=768, C=100 classes, P=4950 pairs.
//   per row: top2(first_out) -> (a<b) -> pair = b*(b-1)/2+a
//            logits[k] = sigma[pair] * cos(x, W[pair,k]),  k=0,1
//            pred = argmax(logits) mapped back through (a,b)
//   out (float32): [0,B) preds, [B,3B) logits row-major (B,2)
//
// R4: streaming (evict-first) loads for x/first_out so the 30MB weight
// table stays L2-resident; load ordering overlaps x-load latency with the
// top-2 shuffle reduction.

#define NROWS   65536
#define DDIM    768
#define NCLS    100
#define F4_PER_LANE 6            // 768 floats / 4 / 32 lanes

__device__ __forceinline__ float warp_sum(float v) {
    #pragma unroll
    for (int o = 16; o; o >>= 1) v += __shfl_xor_sync(0xffffffffu, v, o);
    return v;
}

// evict-first scalar / vector loads (streaming data: read once, never reused)
__device__ __forceinline__ float ldcs_f(const float* p) {
    float v;
    asm volatile("ld.global.cs.f32 %0, [%1];" : "=f"(v) : "l"(p));
    return v;
}
__device__ __forceinline__ float4 ldcs_f4(const float4* p) {
    float4 v;
    asm volatile("ld.global.cs.v4.f32 {%0,%1,%2,%3}, [%4];"
                 : "=f"(v.x), "=f"(v.y), "=f"(v.z), "=f"(v.w) : "l"(p));
    return v;
}

__global__ __launch_bounds__(256, 8)
void mlcl_kernel(const float* __restrict__ x,
                 const float* __restrict__ first_out,
                 const float* __restrict__ weights,
                 const float* __restrict__ sigma,
                 float* __restrict__ out)
{
    const int warp_id = blockIdx.x * 8 + (threadIdx.x >> 5);
    const int lane    = threadIdx.x & 31;
    if (warp_id >= NROWS) return;
    const int row = warp_id;

    // ---- issue first_out loads first (head of the critical path) ----
    const float* fo = first_out + (size_t)row * NCLS;
    float fv[4];
    int   fc[4];
    #pragma unroll
    for (int t = 0; t < 4; ++t) {
        int c = lane + 32 * t;
        fc[t] = c;
        fv[t] = (c < NCLS) ? ldcs_f(fo + c) : -CUDART_INF_F;
    }

    // ---- issue x loads next (independent; latency hidden by top-2 below) ----
    const float4* x4 = (const float4*)(x + (size_t)row * DDIM);
    float4 xf[F4_PER_LANE];
    #pragma unroll
    for (int j = 0; j < F4_PER_LANE; ++j)
        xf[j] = ldcs_f4(x4 + lane + 32 * j);

    // ---- top-2 over first_out[row], jax.lax.top_k tie-break (lower idx) ----
    float v1 = -CUDART_INF_F, v2 = -CUDART_INF_F;
    int   i1 = NCLS,          i2 = NCLS;
    #pragma unroll
    for (int t = 0; t < 4; ++t) {
        float v = fv[t];
        if (v > v1) { v2 = v1; i2 = i1; v1 = v; i1 = fc[t]; }
        else if (v > v2) { v2 = v; i2 = fc[t]; }
        // increasing index order: equal values never displace earlier index
    }
    #pragma unroll
    for (int off = 16; off; off >>= 1) {
        float w1 = __shfl_xor_sync(0xffffffffu, v1, off);
        int   j1 = __shfl_xor_sync(0xffffffffu, i1, off);
        float w2 = __shfl_xor_sync(0xffffffffu, v2, off);
        int   j2 = __shfl_xor_sync(0xffffffffu, i2, off);
        bool w1_best = (w1 > v1) || (w1 == v1 && j1 < i1);
        if (w1_best) {
            bool v1_second = (v1 > w2) || (v1 == w2 && i1 < j2);
            v2 = v1_second ? v1 : w2;
            i2 = v1_second ? i1 : j2;
            v1 = w1; i1 = j1;
        } else {
            bool w1_second = (w1 > v2) || (w1 == v2 && j1 < i2);
            if (w1_second) { v2 = w1; i2 = j1; }
        }
    }
    const int a = min(i1, i2);
    const int b = max(i1, i2);
    const long long pair = (long long)b * (b - 1) / 2 + a;

    // ---- ||x||^2 from the already-landed registers ----
    float xss = 0.f;
    #pragma unroll
    for (int j = 0; j < F4_PER_LANE; ++j) {
        float4 v = xf[j];
        xss = fmaf(v.x, v.x, fmaf(v.y, v.y, fmaf(v.z, v.z, fmaf(v.w, v.w, xss))));
    }
    xss = warp_sum(xss);
    const float xinv = 1.0f / fmaxf(sqrtf(xss), 1e-12f);
    const float sg = __ldg(sigma + pair);

    // ---- dots + weight norms (default caching: keep table in L2) ----
    float logit[2];
    #pragma unroll
    for (int k = 0; k < 2; ++k) {
        const float4* w4 = (const float4*)(weights + ((size_t)pair * 2 + k) * DDIM);
        float dot = 0.f, wss = 0.f;
        #pragma unroll
        for (int j = 0; j < F4_PER_LANE; ++j) {
            float4 w = __ldg(w4 + lane + 32 * j);
            dot = fmaf(w.x, xf[j].x, fmaf(w.y, xf[j].y,
                  fmaf(w.z, xf[j].z, fmaf(w.w, xf[j].w, dot))));
            wss = fmaf(w.x, w.x, fmaf(w.y, w.y,
                  fmaf(w.z, w.z, fmaf(w.w, w.w, wss))));
        }
        dot = warp_sum(dot);
        wss = warp_sum(wss);
        const float winv = 1.0f / fmaxf(sqrtf(wss), 1e-12f);
        logit[k] = sg * dot * xinv * winv;
    }

    if (lane == 0) {
        const int pred = (logit[1] > logit[0]) ? b : a;   // argmax: first on tie
        out[row] = (float)pred;
        out[(size_t)NROWS + 2 * (size_t)row + 0] = logit[0];
        out[(size_t)NROWS + 2 * (size_t)row + 1] = logit[1];
    }
}

extern "C" void kernel_launch(void* const* d_in, const int* in_sizes, int n_in,
                              void* d_out, int out_size) {
    const float* x        = (const float*)d_in[0];
    const float* first_o  = (const float*)d_in[1];
    const float* weights  = (const float*)d_in[2];
    const float* sigma    = (const float*)d_in[3];
    float* out = (float*)d_out;

    const int warps_per_block = 8;
    const int blocks = NROWS / warps_per_block;   // 8192
    mlcl_kernel<<<blocks, 256>>>(x, first_o, weights, sigma, out);
}